// round 4
// baseline (speedup 1.0000x reference)
#include <cuda_runtime.h>
#include <cstdint>
#include <cstring>

#define N_NODES 10000
#define N_EDGES 320000
#define IN_DIM  512
#define CH      128

typedef unsigned long long ull;

// ---------------- scratch (__device__ globals; no allocation allowed) ----------------
__device__ int   g_is64;
__device__ int   g_eidx[2 * N_EDGES];
__device__ int   g_deg[N_NODES];
__device__ int   g_off[N_NODES + 1];
__device__ int   g_cur[N_NODES];
__device__ int   g_csr[N_EDGES];       // source ids grouped by target
__device__ float g_dinv[N_NODES];
__device__ float g_s0[N_NODES];
__device__ float g_h[N_NODES * CH];
__device__ float g_xw[N_NODES * CH];
__device__ float g_z1[N_NODES * CH];
__device__ float g_W2t[IN_DIM * CH];   // [K][CH]
__device__ float g_Wgt[CH * CH];       // [K][CH]

// ---------------- helpers ----------------
__device__ __forceinline__ ull dup2(float x) {
    float2 t = make_float2(x, x);
    ull r; memcpy(&r, &t, 8); return r;
}
__device__ __forceinline__ float sigf(float x) { return 1.0f / (1.0f + __expf(-x)); }

// ---------------- edge index dtype detection + normalization ----------------
__global__ void k_detect(const void* ei) {
    if (threadIdx.x == 0) {
        const long long* p = (const long long*)ei;
        int ok = 1;
        for (int i = 0; i < 64; i++) {
            long long v = p[i];
            if (v < 0 || v >= N_NODES) ok = 0;
        }
        g_is64 = ok;   // if data were int32, packed pairs would be out of range
    }
}

__global__ void k_edges(const void* ei) {
    int i = blockIdx.x * blockDim.x + threadIdx.x;
    if (i < 2 * N_EDGES) {
        int v = g_is64 ? (int)((const long long*)ei)[i] : ((const int*)ei)[i];
        g_eidx[i] = v;
    }
    if (i < N_NODES) { g_deg[i] = 1; g_cur[i] = 0; }  // self-loop; zero cursors
}

__global__ void k_deg() {
    int e = blockIdx.x * blockDim.x + threadIdx.x;
    if (e < N_EDGES) atomicAdd(&g_deg[g_eidx[N_EDGES + e]], 1);
}

__global__ void k_dinv() {
    int i = blockIdx.x * blockDim.x + threadIdx.x;
    if (i < N_NODES) g_dinv[i] = rsqrtf((float)g_deg[i]);
}

// ---------------- exclusive prefix sum over (deg-1), single block ----------------
__global__ void __launch_bounds__(1024) k_scan() {
    __shared__ int sh[1024];
    __shared__ int carry;
    if (threadIdx.x == 0) carry = 0;
    __syncthreads();
    for (int base = 0; base < N_NODES; base += 1024) {
        int i = base + threadIdx.x;
        int v = (i < N_NODES) ? (g_deg[i] - 1) : 0;
        sh[threadIdx.x] = v;
        __syncthreads();
        #pragma unroll
        for (int o = 1; o < 1024; o <<= 1) {
            int t = (threadIdx.x >= o) ? sh[threadIdx.x - o] : 0;
            __syncthreads();
            sh[threadIdx.x] += t;
            __syncthreads();
        }
        if (i < N_NODES) g_off[i] = carry + sh[threadIdx.x] - v;
        __syncthreads();
        if (threadIdx.x == 1023) carry += sh[1023];
        __syncthreads();
    }
    if (threadIdx.x == 0) g_off[N_NODES] = carry;
}

// ---------------- CSR fill: place source ids grouped by target ----------------
__global__ void k_fill() {
    int e = blockIdx.x * blockDim.x + threadIdx.x;
    if (e < N_EDGES) {
        int r = g_eidx[e], c = g_eidx[N_EDGES + e];
        int pos = g_off[c] + atomicAdd(&g_cur[c], 1);
        g_csr[pos] = r;
    }
}

// ---------------- weight transpose: W [R][C] -> Wt [C][R] ----------------
__global__ void k_tr(const float* __restrict__ src, float* __restrict__ dst, int R, int C) {
    int idx = blockIdx.x * blockDim.x + threadIdx.x;
    if (idx < R * C) {
        int r = idx / C, c = idx % C;
        dst[c * R + r] = src[idx];
    }
}

// ---------------- GEMM: out[M][128] = A[M][K] @ Wt[K][128] (+bias) ----------------
// BM=64, BN=128, BK=32, 256 threads, TM=8, TN=4, packed f32x2 FMA.
template<int K>
__global__ void __launch_bounds__(256) k_gemm(const float* __restrict__ A,
                                              const float* __restrict__ Wt,
                                              const float* __restrict__ bias,
                                              float* __restrict__ out, int M) {
    __shared__ ull   As2[64][32];     // A tile, each value duplicated into f32x2
    __shared__ float Ws[32][128];     // W tile [k][n]

    int tid = threadIdx.x;
    int tx = tid & 31;      // 32 column groups of 4
    int ty = tid >> 5;      // 8 row groups of 8
    int row0 = blockIdx.x * 64;

    ull acc[8][2];
    #pragma unroll
    for (int i = 0; i < 8; i++) { acc[i][0] = 0ull; acc[i][1] = 0ull; }

    for (int k0 = 0; k0 < K; k0 += 32) {
        #pragma unroll
        for (int i = 0; i < 2; i++) {
            int s = tid + i * 256;
            int m = s >> 3, kq = s & 7;
            int gm = row0 + m;
            float4 v = make_float4(0.f, 0.f, 0.f, 0.f);
            if (gm < M) v = *(const float4*)(A + (size_t)gm * K + k0 + kq * 4);
            ull* dst = &As2[m][kq * 4];
            dst[0] = dup2(v.x); dst[1] = dup2(v.y); dst[2] = dup2(v.z); dst[3] = dup2(v.w);
        }
        #pragma unroll
        for (int i = 0; i < 4; i++) {
            int s = tid + i * 256;
            int kk = s >> 5, nq = s & 31;
            *(float4*)&Ws[kk][nq * 4] = *(const float4*)(Wt + (size_t)(k0 + kk) * CH + nq * 4);
        }
        __syncthreads();

        #pragma unroll
        for (int k = 0; k < 32; k++) {
            float4 bb = *(const float4*)&Ws[k][tx * 4];
            ull b01, b23;
            memcpy(&b01, &bb.x, 8);
            memcpy(&b23, &bb.z, 8);
            #pragma unroll
            for (int i = 0; i < 8; i++) {
                ull aa = As2[ty * 8 + i][k];
                asm("fma.rn.f32x2 %0, %1, %2, %0;" : "+l"(acc[i][0]) : "l"(aa), "l"(b01));
                asm("fma.rn.f32x2 %0, %1, %2, %0;" : "+l"(acc[i][1]) : "l"(aa), "l"(b23));
            }
        }
        __syncthreads();
    }

    float4 bv = make_float4(0.f, 0.f, 0.f, 0.f);
    if (bias) bv = *(const float4*)(bias + tx * 4);
    #pragma unroll
    for (int i = 0; i < 8; i++) {
        int gm = row0 + ty * 8 + i;
        if (gm < M) {
            float2 c01, c23;
            memcpy(&c01, &acc[i][0], 8);
            memcpy(&c23, &acc[i][1], 8);
            float4 o = make_float4(c01.x + bv.x, c01.y + bv.y, c23.x + bv.z, c23.y + bv.w);
            *(float4*)(out + (size_t)gm * CH + tx * 4) = o;
        }
    }
}

// ---------------- row l2-normalize * 1.8 (in place on g_h), warp per row ----------------
__global__ void k_rownorm() {
    int g = blockIdx.x * blockDim.x + threadIdx.x;
    int row = g >> 5, lane = g & 31;
    if (row >= N_NODES) return;
    float4* h4 = (float4*)g_h;
    float4 v = h4[(size_t)row * 32 + lane];
    float ss = v.x * v.x + v.y * v.y + v.z * v.z + v.w * v.w;
    #pragma unroll
    for (int o = 16; o > 0; o >>= 1) ss += __shfl_xor_sync(0xffffffffu, ss, o);
    float s = 1.8f / fmaxf(sqrtf(ss), 1e-12f);
    v.x *= s; v.y *= s; v.z *= s; v.w *= s;
    h4[(size_t)row * 32 + lane] = v;
}

// ---------------- CSR aggregation: warp per target node, no atomics ----------------
__global__ void __launch_bounds__(256) k_aggcsr(const float* __restrict__ bg) {
    int g = blockIdx.x * blockDim.x + threadIdx.x;
    int node = g >> 5, lane = g & 31;
    if (node >= N_NODES) return;
    const float4* xw4 = (const float4*)g_xw;
    float dc = g_dinv[node];

    // self-loop: weight dinv[c]^2; accumulate pre-scaled by dinv[r], final *dinv[c]
    float4 acc = xw4[(size_t)node * 32 + lane];
    acc.x *= dc; acc.y *= dc; acc.z *= dc; acc.w *= dc;

    int j = g_off[node], end = g_off[node + 1];
    int r_next = (j < end) ? g_csr[j] : 0;
    while (j < end) {
        int r = r_next;
        if (j + 1 < end) r_next = g_csr[j + 1];
        float w = g_dinv[r];
        float4 v = xw4[(size_t)r * 32 + lane];
        acc.x += v.x * w; acc.y += v.y * w; acc.z += v.z * w; acc.w += v.w * w;
        j++;
    }

    float4 b = ((const float4*)bg)[lane];
    float4 o = make_float4(acc.x * dc + b.x, acc.y * dc + b.y,
                           acc.z * dc + b.z, acc.w * dc + b.w);
    ((float4*)g_z1)[(size_t)node * 32 + lane] = o;
}

// ---------------- z2 branch: s0[row] = 0.8 * a / max(||(a,b)||, eps) ----------------
#define ZR 16
__global__ void __launch_bounds__(256) k_z2(const float* __restrict__ x2,
                                            const float* __restrict__ W22) {
    __shared__ float4 w0s[1250];
    __shared__ float4 w1s[1250];
    __shared__ float  part[8 * ZR * 2];
    int tid = threadIdx.x;
    int lane = tid & 31, warp = tid >> 5;
    int rbase = blockIdx.x * ZR;

    float a0[ZR], a1[ZR];
    #pragma unroll
    for (int r = 0; r < ZR; r++) { a0[r] = 0.f; a1[r] = 0.f; }

    for (int half = 0; half < 2; half++) {
        int k0 = half * 5000;
        for (int i = tid; i < 1250; i += 256) {
            w0s[i] = *(const float4*)(W22 + k0 + i * 4);
            w1s[i] = *(const float4*)(W22 + N_NODES + k0 + i * 4);
        }
        __syncthreads();
        #pragma unroll
        for (int r = 0; r < ZR; r++) {
            const float4* xr = (const float4*)(x2 + (size_t)(rbase + r) * N_NODES + k0);
            float s0a = 0.f, s1a = 0.f;
            for (int i = tid; i < 1250; i += 256) {
                float4 xv = xr[i];
                float4 wa = w0s[i];
                float4 wb = w1s[i];
                s0a += xv.x * wa.x + xv.y * wa.y + xv.z * wa.z + xv.w * wa.w;
                s1a += xv.x * wb.x + xv.y * wb.y + xv.z * wb.z + xv.w * wb.w;
            }
            a0[r] += s0a; a1[r] += s1a;
        }
        __syncthreads();
    }

    #pragma unroll
    for (int r = 0; r < ZR; r++) {
        #pragma unroll
        for (int o = 16; o > 0; o >>= 1) {
            a0[r] += __shfl_xor_sync(0xffffffffu, a0[r], o);
            a1[r] += __shfl_xor_sync(0xffffffffu, a1[r], o);
        }
    }
    if (lane == 0) {
        #pragma unroll
        for (int r = 0; r < ZR; r++) {
            part[warp * ZR * 2 + r * 2 + 0] = a0[r];
            part[warp * ZR * 2 + r * 2 + 1] = a1[r];
        }
    }
    __syncthreads();
    if (tid < ZR) {
        float a = 0.f, b = 0.f;
        #pragma unroll
        for (int w = 0; w < 8; w++) {
            a += part[w * ZR * 2 + tid * 2 + 0];
            b += part[w * ZR * 2 + tid * 2 + 1];
        }
        g_s0[rbase + tid] = 0.8f * a / fmaxf(sqrtf(a * a + b * b), 1e-12f);
    }
}

// ---------------- final per-edge decoder, warp per edge ----------------
__global__ void __launch_bounds__(256) k_final(float* __restrict__ out) {
    int g = blockIdx.x * blockDim.x + threadIdx.x;
    int e = g >> 5, lane = g & 31;
    if (e >= N_EDGES) return;
    int r = g_eidx[e], c = g_eidx[N_EDGES + e];
    const float4* z4 = (const float4*)g_z1;
    float4 a = z4[(size_t)r * 32 + lane];
    float4 b = z4[(size_t)c * 32 + lane];
    float p = a.x * b.x + a.y * b.y + a.z * b.z + a.w * b.w;
    #pragma unroll
    for (int o = 16; o > 0; o >>= 1) p += __shfl_xor_sync(0xffffffffu, p, o);
    if (lane == 0) {
        float sf = sigf(p);
        float vn = g_s0[r] + g_s0[c];
        out[e] = sf * sf + (1.0f - sf) * sigf(vn);
    }
}

// ---------------- launch ----------------
static void* sym_addr(const void* sym) {
    void* p = nullptr;
    cudaGetSymbolAddress(&p, sym);
    return p;
}

extern "C" void kernel_launch(void* const* d_in, const int* in_sizes, int n_in,
                              void* d_out, int out_size) {
    const float* x   = (const float*)d_in[0];
    const float* x2  = (const float*)d_in[1];
    const float* W2  = (const float*)d_in[2];
    const float* b2  = (const float*)d_in[3];
    const float* Wg  = (const float*)d_in[4];
    const float* bg  = (const float*)d_in[5];
    const float* W22 = (const float*)d_in[6];
    const void*  ei  = d_in[7];
    float* out = (float*)d_out;

    float* p_h   = (float*)sym_addr(g_h);
    float* p_xw  = (float*)sym_addr(g_xw);
    float* p_W2t = (float*)sym_addr(g_W2t);
    float* p_Wgt = (float*)sym_addr(g_Wgt);

    k_detect<<<1, 32>>>(ei);
    k_edges<<<(2 * N_EDGES + 255) / 256, 256>>>(ei);
    k_deg<<<(N_EDGES + 255) / 256, 256>>>();
    k_dinv<<<(N_NODES + 255) / 256, 256>>>();
    k_scan<<<1, 1024>>>();
    k_fill<<<(N_EDGES + 255) / 256, 256>>>();

    k_tr<<<(IN_DIM * CH + 255) / 256, 256>>>(W2, p_W2t, CH, IN_DIM);
    k_tr<<<(CH * CH + 255) / 256, 256>>>(Wg, p_Wgt, CH, CH);

    k_gemm<IN_DIM><<<(N_NODES + 63) / 64, 256>>>(x, p_W2t, b2, p_h, N_NODES);
    k_rownorm<<<(N_NODES * 32 + 255) / 256, 256>>>();
    k_gemm<CH><<<(N_NODES + 63) / 64, 256>>>(p_h, p_Wgt, nullptr, p_xw, N_NODES);

    k_aggcsr<<<(N_NODES * 32 + 255) / 256, 256>>>(bg);

    k_z2<<<N_NODES / ZR, 256>>>(x2, W22);

    k_final<<<(N_EDGES * 32 + 255) / 256, 256>>>(out);
}

// round 5
// speedup vs baseline: 1.4107x; 1.4107x over previous
#include <cuda_runtime.h>
#include <cstdint>
#include <cstring>

#define N_NODES 10000
#define N_EDGES 320000
#define IN_DIM  512
#define CH      128

typedef unsigned long long ull;

// ---------------- scratch (__device__ globals; no allocation allowed) ----------------
__device__ int   g_is64;
__device__ int   g_eidx[2 * N_EDGES];
__device__ int   g_deg[N_NODES];
__device__ float g_dinv[N_NODES];
__device__ float g_s0[N_NODES];
__device__ float g_h[N_NODES * CH];
__device__ float g_xw[N_NODES * CH];
__device__ float g_z1[N_NODES * CH];
__device__ float g_W2t[IN_DIM * CH];   // [K][CH]
__device__ float g_Wgt[CH * CH];       // [K][CH]

// ---------------- helpers ----------------
__device__ __forceinline__ ull dup2(float x) {
    float2 t = make_float2(x, x);
    ull r; memcpy(&r, &t, 8); return r;
}
__device__ __forceinline__ float sigf(float x) { return 1.0f / (1.0f + __expf(-x)); }

// ---------------- edge index dtype detection + normalization ----------------
__global__ void k_detect(const void* ei) {
    if (threadIdx.x == 0) {
        const long long* p = (const long long*)ei;
        int ok = 1;
        for (int i = 0; i < 64; i++) {
            long long v = p[i];
            if (v < 0 || v >= N_NODES) ok = 0;
        }
        g_is64 = ok;   // if data were int32, packed pairs would be out of range
    }
}

__global__ void k_edges(const void* ei) {
    int i = blockIdx.x * blockDim.x + threadIdx.x;
    if (i < 2 * N_EDGES) {
        int v = g_is64 ? (int)((const long long*)ei)[i] : ((const int*)ei)[i];
        g_eidx[i] = v;
    }
    if (i < N_NODES) g_deg[i] = 1;  // self-loop
}

__global__ void k_deg() {
    int e = blockIdx.x * blockDim.x + threadIdx.x;
    if (e < N_EDGES) atomicAdd(&g_deg[g_eidx[N_EDGES + e]], 1);
}

__global__ void k_dinv() {
    int i = blockIdx.x * blockDim.x + threadIdx.x;
    if (i < N_NODES) g_dinv[i] = rsqrtf((float)g_deg[i]);
}

// ---------------- weight transpose: W [R][C] -> Wt [C][R] ----------------
__global__ void k_tr(const float* __restrict__ src, float* __restrict__ dst, int R, int C) {
    int idx = blockIdx.x * blockDim.x + threadIdx.x;
    if (idx < R * C) {
        int r = idx / C, c = idx % C;
        dst[c * R + r] = src[idx];
    }
}

// ---------------- GEMM: out[M][128] = A[M][K] @ Wt[K][128] (+bias) ----------------
// BM=128, BN=128, BK=32, 256 threads, TM=8, TN=8, packed f32x2 FMA.
// A in smem as plain float (stride 33 to avoid bank conflicts), dup'd in registers.
template<int K>
__global__ void __launch_bounds__(256) k_gemm(const float* __restrict__ A,
                                              const float* __restrict__ Wt,
                                              const float* __restrict__ bias,
                                              float* __restrict__ out, int M) {
    __shared__ float As[128][33];     // [m][k], padded stride
    __shared__ float Ws[32][128];     // [k][n]

    int tid = threadIdx.x;
    int tx = tid & 15;      // 16 column groups of 8
    int ty = tid >> 4;      // 16 row groups of 8
    int row0 = blockIdx.x * 128;

    ull acc[8][4];
    #pragma unroll
    for (int i = 0; i < 8; i++)
        #pragma unroll
        for (int j = 0; j < 4; j++) acc[i][j] = 0ull;

    for (int k0 = 0; k0 < K; k0 += 32) {
        // load A tile: 128 rows x 32 k (1024 float4 slots)
        #pragma unroll
        for (int i = 0; i < 4; i++) {
            int s = tid + i * 256;
            int m = s >> 3, kq = s & 7;
            int gm = row0 + m;
            float4 v = make_float4(0.f, 0.f, 0.f, 0.f);
            if (gm < M) v = *(const float4*)(A + (size_t)gm * K + k0 + kq * 4);
            float* dst = &As[m][kq * 4];
            dst[0] = v.x; dst[1] = v.y; dst[2] = v.z; dst[3] = v.w;
        }
        // load W tile: 32 k x 128 n (1024 float4 slots)
        #pragma unroll
        for (int i = 0; i < 4; i++) {
            int s = tid + i * 256;
            int kk = s >> 5, nq = s & 31;
            *(float4*)&Ws[kk][nq * 4] = *(const float4*)(Wt + (size_t)(k0 + kk) * CH + nq * 4);
        }
        __syncthreads();

        #pragma unroll
        for (int k = 0; k < 32; k++) {
            float4 b0 = *(const float4*)&Ws[k][tx * 8];
            float4 b1 = *(const float4*)&Ws[k][tx * 8 + 4];
            ull bb[4];
            memcpy(&bb[0], &b0.x, 8); memcpy(&bb[1], &b0.z, 8);
            memcpy(&bb[2], &b1.x, 8); memcpy(&bb[3], &b1.z, 8);
            #pragma unroll
            for (int i = 0; i < 8; i++) {
                ull aa = dup2(As[ty * 8 + i][k]);
                #pragma unroll
                for (int j = 0; j < 4; j++)
                    asm("fma.rn.f32x2 %0, %1, %2, %0;" : "+l"(acc[i][j]) : "l"(aa), "l"(bb[j]));
            }
        }
        __syncthreads();
    }

    float4 bv0 = make_float4(0.f, 0.f, 0.f, 0.f);
    float4 bv1 = make_float4(0.f, 0.f, 0.f, 0.f);
    if (bias) {
        bv0 = *(const float4*)(bias + tx * 8);
        bv1 = *(const float4*)(bias + tx * 8 + 4);
    }
    #pragma unroll
    for (int i = 0; i < 8; i++) {
        int gm = row0 + ty * 8 + i;
        if (gm < M) {
            float2 c0, c1, c2, c3;
            memcpy(&c0, &acc[i][0], 8); memcpy(&c1, &acc[i][1], 8);
            memcpy(&c2, &acc[i][2], 8); memcpy(&c3, &acc[i][3], 8);
            float4 o0 = make_float4(c0.x + bv0.x, c0.y + bv0.y, c1.x + bv0.z, c1.y + bv0.w);
            float4 o1 = make_float4(c2.x + bv1.x, c2.y + bv1.y, c3.x + bv1.z, c3.y + bv1.w);
            *(float4*)(out + (size_t)gm * CH + tx * 8) = o0;
            *(float4*)(out + (size_t)gm * CH + tx * 8 + 4) = o1;
        }
    }
}

// ---------------- row l2-normalize * 1.8 (in place on g_h), warp per row ----------------
__global__ void k_rownorm() {
    int g = blockIdx.x * blockDim.x + threadIdx.x;
    int row = g >> 5, lane = g & 31;
    if (row >= N_NODES) return;
    float4* h4 = (float4*)g_h;
    float4 v = h4[(size_t)row * 32 + lane];
    float ss = v.x * v.x + v.y * v.y + v.z * v.z + v.w * v.w;
    #pragma unroll
    for (int o = 16; o > 0; o >>= 1) ss += __shfl_xor_sync(0xffffffffu, ss, o);
    float s = 1.8f / fmaxf(sqrtf(ss), 1e-12f);
    v.x *= s; v.y *= s; v.z *= s; v.w *= s;
    h4[(size_t)row * 32 + lane] = v;
}

// ---------------- z1 init: z1 = bg + xw * dinv^2 (self-loop term) ----------------
__global__ void k_z1init(const float* __restrict__ bg) {
    int i4 = blockIdx.x * blockDim.x + threadIdx.x;
    if (i4 >= N_NODES * 32) return;
    int n = i4 >> 5, c4 = i4 & 31;
    float d = g_dinv[n];
    float w = d * d;
    float4 xv = ((const float4*)g_xw)[i4];
    float4 b = ((const float4*)bg)[c4];
    ((float4*)g_z1)[i4] = make_float4(b.x + xv.x * w, b.y + xv.y * w,
                                      b.z + xv.z * w, b.w + xv.w * w);
}

// ---------------- edge aggregation: z1[c] += dinv[r]*dinv[c] * xw[r], warp/edge ----------------
// One red.global.add.v4.f32 per lane (4x fewer L2 atomic ops than scalar).
__global__ void __launch_bounds__(256) k_agg() {
    int g = blockIdx.x * blockDim.x + threadIdx.x;
    int e = g >> 5, lane = g & 31;
    if (e >= N_EDGES) return;
    int r = g_eidx[e], c = g_eidx[N_EDGES + e];
    float w = g_dinv[r] * g_dinv[c];
    float4 v = ((const float4*)g_xw)[(size_t)r * 32 + lane];
    float* dst = g_z1 + (size_t)c * CH + lane * 4;
    asm volatile("red.global.add.v4.f32 [%0], {%1, %2, %3, %4};"
                 :: "l"(dst), "f"(v.x * w), "f"(v.y * w), "f"(v.z * w), "f"(v.w * w)
                 : "memory");
}

// ---------------- z2 branch: s0[row] = 0.8 * a / max(||(a,b)||, eps) ----------------
#define ZR 16
__global__ void __launch_bounds__(256) k_z2(const float* __restrict__ x2,
                                            const float* __restrict__ W22) {
    __shared__ float4 w0s[1250];
    __shared__ float4 w1s[1250];
    __shared__ float  part[8 * ZR * 2];
    int tid = threadIdx.x;
    int lane = tid & 31, warp = tid >> 5;
    int rbase = blockIdx.x * ZR;

    float a0[ZR], a1[ZR];
    #pragma unroll
    for (int r = 0; r < ZR; r++) { a0[r] = 0.f; a1[r] = 0.f; }

    for (int half = 0; half < 2; half++) {
        int k0 = half * 5000;
        for (int i = tid; i < 1250; i += 256) {
            w0s[i] = *(const float4*)(W22 + k0 + i * 4);
            w1s[i] = *(const float4*)(W22 + N_NODES + k0 + i * 4);
        }
        __syncthreads();
        #pragma unroll
        for (int r = 0; r < ZR; r++) {
            const float4* xr = (const float4*)(x2 + (size_t)(rbase + r) * N_NODES + k0);
            float s0a = 0.f, s1a = 0.f;
            for (int i = tid; i < 1250; i += 256) {
                float4 xv = xr[i];
                float4 wa = w0s[i];
                float4 wb = w1s[i];
                s0a += xv.x * wa.x + xv.y * wa.y + xv.z * wa.z + xv.w * wa.w;
                s1a += xv.x * wb.x + xv.y * wb.y + xv.z * wb.z + xv.w * wb.w;
            }
            a0[r] += s0a; a1[r] += s1a;
        }
        __syncthreads();
    }

    #pragma unroll
    for (int r = 0; r < ZR; r++) {
        #pragma unroll
        for (int o = 16; o > 0; o >>= 1) {
            a0[r] += __shfl_xor_sync(0xffffffffu, a0[r], o);
            a1[r] += __shfl_xor_sync(0xffffffffu, a1[r], o);
        }
    }
    if (lane == 0) {
        #pragma unroll
        for (int r = 0; r < ZR; r++) {
            part[warp * ZR * 2 + r * 2 + 0] = a0[r];
            part[warp * ZR * 2 + r * 2 + 1] = a1[r];
        }
    }
    __syncthreads();
    if (tid < ZR) {
        float a = 0.f, b = 0.f;
        #pragma unroll
        for (int w = 0; w < 8; w++) {
            a += part[w * ZR * 2 + tid * 2 + 0];
            b += part[w * ZR * 2 + tid * 2 + 1];
        }
        g_s0[rbase + tid] = 0.8f * a / fmaxf(sqrtf(a * a + b * b), 1e-12f);
    }
}

// ---------------- final per-edge decoder, warp per edge ----------------
__global__ void __launch_bounds__(256) k_final(float* __restrict__ out) {
    int g = blockIdx.x * blockDim.x + threadIdx.x;
    int e = g >> 5, lane = g & 31;
    if (e >= N_EDGES) return;
    int r = g_eidx[e], c = g_eidx[N_EDGES + e];
    const float4* z4 = (const float4*)g_z1;
    float4 a = z4[(size_t)r * 32 + lane];
    float4 b = z4[(size_t)c * 32 + lane];
    float p = a.x * b.x + a.y * b.y + a.z * b.z + a.w * b.w;
    #pragma unroll
    for (int o = 16; o > 0; o >>= 1) p += __shfl_xor_sync(0xffffffffu, p, o);
    if (lane == 0) {
        float sf = sigf(p);
        float vn = g_s0[r] + g_s0[c];
        out[e] = sf * sf + (1.0f - sf) * sigf(vn);
    }
}

// ---------------- launch ----------------
static void* sym_addr(const void* sym) {
    void* p = nullptr;
    cudaGetSymbolAddress(&p, sym);
    return p;
}

extern "C" void kernel_launch(void* const* d_in, const int* in_sizes, int n_in,
                              void* d_out, int out_size) {
    const float* x   = (const float*)d_in[0];
    const float* x2  = (const float*)d_in[1];
    const float* W2  = (const float*)d_in[2];
    const float* b2  = (const float*)d_in[3];
    const float* Wg  = (const float*)d_in[4];
    const float* bg  = (const float*)d_in[5];
    const float* W22 = (const float*)d_in[6];
    const void*  ei  = d_in[7];
    float* out = (float*)d_out;

    float* p_h   = (float*)sym_addr(g_h);
    float* p_xw  = (float*)sym_addr(g_xw);
    float* p_W2t = (float*)sym_addr(g_W2t);
    float* p_Wgt = (float*)sym_addr(g_Wgt);

    // Launch order chosen so the ncu capture slot (4th launch) hits k_z2.
    k_detect<<<1, 32>>>(ei);                                   // 1
    k_edges<<<(2 * N_EDGES + 255) / 256, 256>>>(ei);           // 2
    k_deg<<<(N_EDGES + 255) / 256, 256>>>();                   // 3
    k_z2<<<N_NODES / ZR, 256>>>(x2, W22);                      // 4  <- profiled
    k_dinv<<<(N_NODES + 255) / 256, 256>>>();                  // 5

    k_tr<<<(IN_DIM * CH + 255) / 256, 256>>>(W2, p_W2t, CH, IN_DIM);
    k_tr<<<(CH * CH + 255) / 256, 256>>>(Wg, p_Wgt, CH, CH);

    k_gemm<IN_DIM><<<(N_NODES + 127) / 128, 256>>>(x, p_W2t, b2, p_h, N_NODES);
    k_rownorm<<<(N_NODES * 32 + 255) / 256, 256>>>();
    k_gemm<CH><<<(N_NODES + 127) / 128, 256>>>(p_h, p_Wgt, nullptr, p_xw, N_NODES);

    k_z1init<<<(N_NODES * 32 + 255) / 256, 256>>>(bg);
    k_agg<<<(N_EDGES * 32 + 255) / 256, 256>>>();

    k_final<<<(N_EDGES * 32 + 255) / 256, 256>>>(out);
}

// round 7
// speedup vs baseline: 2.1807x; 1.5458x over previous
#include <cuda_runtime.h>
#include <cstdint>
#include <cstring>

#define N_NODES 10000
#define N_EDGES 320000
#define IN_DIM  512
#define CH      128

typedef unsigned long long ull;

// ---------------- scratch (__device__ globals; no allocation allowed) ----------------
__device__ int   g_is64;
__device__ int   g_eidx[2 * N_EDGES];
__device__ int   g_deg[N_NODES];
__device__ float g_dinv[N_NODES];
__device__ float g_s0[N_NODES];
__device__ float g_h[N_NODES * CH];
__device__ float g_xw[N_NODES * CH];
__device__ float g_z1[N_NODES * CH];
__device__ float g_W2t[IN_DIM * CH];   // [K][CH]
__device__ float g_Wgt[CH * CH];       // [K][CH]

// ---------------- helpers ----------------
__device__ __forceinline__ ull dup2(float x) {
    float2 t = make_float2(x, x);
    ull r; memcpy(&r, &t, 8); return r;
}
__device__ __forceinline__ float sigf(float x) { return 1.0f / (1.0f + __expf(-x)); }

// ---------------- edge index dtype detection + normalization ----------------
__global__ void k_detect(const void* ei) {
    if (threadIdx.x == 0) {
        const long long* p = (const long long*)ei;
        int ok = 1;
        for (int i = 0; i < 64; i++) {
            long long v = p[i];
            if (v < 0 || v >= N_NODES) ok = 0;
        }
        g_is64 = ok;   // if data were int32, packed pairs would be out of range
    }
}

__global__ void k_edges(const void* ei) {
    int i = blockIdx.x * blockDim.x + threadIdx.x;
    if (i < 2 * N_EDGES) {
        int v = g_is64 ? (int)((const long long*)ei)[i] : ((const int*)ei)[i];
        g_eidx[i] = v;
    }
    if (i < N_NODES) g_deg[i] = 1;  // self-loop
}

__global__ void k_deg() {
    int e = blockIdx.x * blockDim.x + threadIdx.x;
    if (e < N_EDGES) atomicAdd(&g_deg[g_eidx[N_EDGES + e]], 1);
}

__global__ void k_dinv() {
    int i = blockIdx.x * blockDim.x + threadIdx.x;
    if (i < N_NODES) g_dinv[i] = rsqrtf((float)g_deg[i]);
}

// ---------------- weight transpose: W [R][C] -> Wt [C][R] ----------------
__global__ void k_tr(const float* __restrict__ src, float* __restrict__ dst, int R, int C) {
    int idx = blockIdx.x * blockDim.x + threadIdx.x;
    if (idx < R * C) {
        int r = idx / C, c = idx % C;
        dst[c * R + r] = src[idx];
    }
}

// ---------------- GEMM: out[M][128] = A[M][K] @ Wt[K][128] (+bias) ----------------
// BM=128, BN=128, BK=32, 256 threads, TM=8, TN=8, packed f32x2 FMA.
template<int K>
__global__ void __launch_bounds__(256) k_gemm(const float* __restrict__ A,
                                              const float* __restrict__ Wt,
                                              const float* __restrict__ bias,
                                              float* __restrict__ out, int M) {
    __shared__ float As[128][33];     // [m][k], padded stride
    __shared__ float Ws[32][128];     // [k][n]

    int tid = threadIdx.x;
    int tx = tid & 15;      // 16 column groups of 8
    int ty = tid >> 4;      // 16 row groups of 8
    int row0 = blockIdx.x * 128;

    ull acc[8][4];
    #pragma unroll
    for (int i = 0; i < 8; i++)
        #pragma unroll
        for (int j = 0; j < 4; j++) acc[i][j] = 0ull;

    for (int k0 = 0; k0 < K; k0 += 32) {
        #pragma unroll
        for (int i = 0; i < 4; i++) {
            int s = tid + i * 256;
            int m = s >> 3, kq = s & 7;
            int gm = row0 + m;
            float4 v = make_float4(0.f, 0.f, 0.f, 0.f);
            if (gm < M) v = *(const float4*)(A + (size_t)gm * K + k0 + kq * 4);
            float* dst = &As[m][kq * 4];
            dst[0] = v.x; dst[1] = v.y; dst[2] = v.z; dst[3] = v.w;
        }
        #pragma unroll
        for (int i = 0; i < 4; i++) {
            int s = tid + i * 256;
            int kk = s >> 5, nq = s & 31;
            *(float4*)&Ws[kk][nq * 4] = *(const float4*)(Wt + (size_t)(k0 + kk) * CH + nq * 4);
        }
        __syncthreads();

        #pragma unroll
        for (int k = 0; k < 32; k++) {
            float4 b0 = *(const float4*)&Ws[k][tx * 8];
            float4 b1 = *(const float4*)&Ws[k][tx * 8 + 4];
            ull bb[4];
            memcpy(&bb[0], &b0.x, 8); memcpy(&bb[1], &b0.z, 8);
            memcpy(&bb[2], &b1.x, 8); memcpy(&bb[3], &b1.z, 8);
            #pragma unroll
            for (int i = 0; i < 8; i++) {
                ull aa = dup2(As[ty * 8 + i][k]);
                #pragma unroll
                for (int j = 0; j < 4; j++)
                    asm("fma.rn.f32x2 %0, %1, %2, %0;" : "+l"(acc[i][j]) : "l"(aa), "l"(bb[j]));
            }
        }
        __syncthreads();
    }

    float4 bv0 = make_float4(0.f, 0.f, 0.f, 0.f);
    float4 bv1 = make_float4(0.f, 0.f, 0.f, 0.f);
    if (bias) {
        bv0 = *(const float4*)(bias + tx * 8);
        bv1 = *(const float4*)(bias + tx * 8 + 4);
    }
    #pragma unroll
    for (int i = 0; i < 8; i++) {
        int gm = row0 + ty * 8 + i;
        if (gm < M) {
            float2 c0, c1, c2, c3;
            memcpy(&c0, &acc[i][0], 8); memcpy(&c1, &acc[i][1], 8);
            memcpy(&c2, &acc[i][2], 8); memcpy(&c3, &acc[i][3], 8);
            float4 o0 = make_float4(c0.x + bv0.x, c0.y + bv0.y, c1.x + bv0.z, c1.y + bv0.w);
            float4 o1 = make_float4(c2.x + bv1.x, c2.y + bv1.y, c3.x + bv1.z, c3.y + bv1.w);
            *(float4*)(out + (size_t)gm * CH + tx * 8) = o0;
            *(float4*)(out + (size_t)gm * CH + tx * 8 + 4) = o1;
        }
    }
}

// ---------------- row l2-normalize * 1.8 (in place on g_h), warp per row ----------------
__global__ void k_rownorm() {
    int g = blockIdx.x * blockDim.x + threadIdx.x;
    int row = g >> 5, lane = g & 31;
    if (row >= N_NODES) return;
    float4* h4 = (float4*)g_h;
    float4 v = h4[(size_t)row * 32 + lane];
    float ss = v.x * v.x + v.y * v.y + v.z * v.z + v.w * v.w;
    #pragma unroll
    for (int o = 16; o > 0; o >>= 1) ss += __shfl_xor_sync(0xffffffffu, ss, o);
    float s = 1.8f / fmaxf(sqrtf(ss), 1e-12f);
    v.x *= s; v.y *= s; v.z *= s; v.w *= s;
    h4[(size_t)row * 32 + lane] = v;
}

// ---------------- z1 init: z1 = bg + xw * dinv^2 (self-loop term) ----------------
__global__ void k_z1init(const float* __restrict__ bg) {
    int i4 = blockIdx.x * blockDim.x + threadIdx.x;
    if (i4 >= N_NODES * 32) return;
    int n = i4 >> 5, c4 = i4 & 31;
    float d = g_dinv[n];
    float w = d * d;
    float4 xv = ((const float4*)g_xw)[i4];
    float4 b = ((const float4*)bg)[c4];
    ((float4*)g_z1)[i4] = make_float4(b.x + xv.x * w, b.y + xv.y * w,
                                      b.z + xv.z * w, b.w + xv.w * w);
}

// ---------------- edge aggregation: z1[c] += dinv[r]*dinv[c] * xw[r], warp/edge ----------------
__global__ void __launch_bounds__(256) k_agg() {
    int g = blockIdx.x * blockDim.x + threadIdx.x;
    int e = g >> 5, lane = g & 31;
    if (e >= N_EDGES) return;
    int r = g_eidx[e], c = g_eidx[N_EDGES + e];
    float w = g_dinv[r] * g_dinv[c];
    float4 v = ((const float4*)g_xw)[(size_t)r * 32 + lane];
    float* dst = g_z1 + (size_t)c * CH + lane * 4;
    asm volatile("red.global.add.v4.f32 [%0], {%1, %2, %3, %4};"
                 :: "l"(dst), "f"(v.x * w), "f"(v.y * w), "f"(v.z * w), "f"(v.w * w)
                 : "memory");
}

// ---------------- z2 branch: one block per row, W22 from L1/L2, no smem tiles ----------------
__global__ void __launch_bounds__(256) k_z2(const float* __restrict__ x2,
                                            const float* __restrict__ W22) {
    int row = blockIdx.x;
    int tid = threadIdx.x;
    int lane = tid & 31, warp = tid >> 5;
    const float4* xr = (const float4*)(x2 + (size_t)row * N_NODES);
    const float4* w0 = (const float4*)W22;
    const float4* w1 = (const float4*)(W22 + N_NODES);

    float a = 0.f, b = 0.f;
    // 2500 float4 per row; 256 threads -> ~10 iters, independent loads (high MLP)
    for (int i = tid; i < N_NODES / 4; i += 256) {
        float4 xv = __ldcs(&xr[i]);   // streamed, read once
        float4 wa = __ldg(&w0[i]);    // L1-resident after first row on this SM
        float4 wb = __ldg(&w1[i]);
        a += xv.x * wa.x + xv.y * wa.y + xv.z * wa.z + xv.w * wa.w;
        b += xv.x * wb.x + xv.y * wb.y + xv.z * wb.z + xv.w * wb.w;
    }
    #pragma unroll
    for (int o = 16; o > 0; o >>= 1) {
        a += __shfl_xor_sync(0xffffffffu, a, o);
        b += __shfl_xor_sync(0xffffffffu, b, o);
    }
    __shared__ float sa[8], sb[8];
    if (lane == 0) { sa[warp] = a; sb[warp] = b; }
    __syncthreads();
    if (tid == 0) {
        float aa = 0.f, bbv = 0.f;
        #pragma unroll
        for (int w = 0; w < 8; w++) { aa += sa[w]; bbv += sb[w]; }
        g_s0[row] = 0.8f * aa / fmaxf(sqrtf(aa * aa + bbv * bbv), 1e-12f);
    }
}

// ---------------- final per-edge decoder, warp per edge ----------------
__global__ void __launch_bounds__(256) k_final(float* __restrict__ out) {
    int g = blockIdx.x * blockDim.x + threadIdx.x;
    int e = g >> 5, lane = g & 31;
    if (e >= N_EDGES) return;
    int r = g_eidx[e], c = g_eidx[N_EDGES + e];
    const float4* z4 = (const float4*)g_z1;
    float4 a = z4[(size_t)r * 32 + lane];
    float4 b = z4[(size_t)c * 32 + lane];
    float p = a.x * b.x + a.y * b.y + a.z * b.z + a.w * b.w;
    #pragma unroll
    for (int o = 16; o > 0; o >>= 1) p += __shfl_xor_sync(0xffffffffu, p, o);
    if (lane == 0) {
        float sf = sigf(p);
        float vn = g_s0[r] + g_s0[c];
        out[e] = sf * sf + (1.0f - sf) * sigf(vn);
    }
}

// ---------------- launch ----------------
static void* sym_addr(const void* sym) {
    void* p = nullptr;
    cudaGetSymbolAddress(&p, sym);
    return p;
}

extern "C" void kernel_launch(void* const* d_in, const int* in_sizes, int n_in,
                              void* d_out, int out_size) {
    const float* x   = (const float*)d_in[0];
    const float* x2  = (const float*)d_in[1];
    const float* W2  = (const float*)d_in[2];
    const float* b2  = (const float*)d_in[3];
    const float* Wg  = (const float*)d_in[4];
    const float* bg  = (const float*)d_in[5];
    const float* W22 = (const float*)d_in[6];
    const void*  ei  = d_in[7];
    float* out = (float*)d_out;

    float* p_h   = (float*)sym_addr(g_h);
    float* p_xw  = (float*)sym_addr(g_xw);
    float* p_W2t = (float*)sym_addr(g_W2t);
    float* p_Wgt = (float*)sym_addr(g_Wgt);

    // Launch order: slot #4 (profiled) = k_gemm<512>.
    k_detect<<<1, 32>>>(ei);                                         // 1
    k_edges<<<(2 * N_EDGES + 255) / 256, 256>>>(ei);                 // 2
    k_tr<<<(IN_DIM * CH + 255) / 256, 256>>>(W2, p_W2t, CH, IN_DIM); // 3
    k_gemm<IN_DIM><<<(N_NODES + 127) / 128, 256>>>(x, p_W2t, b2, p_h, N_NODES); // 4 <- profiled
    k_deg<<<(N_EDGES + 255) / 256, 256>>>();                         // 5
    k_dinv<<<(N_NODES + 255) / 256, 256>>>();
    k_tr<<<(CH * CH + 255) / 256, 256>>>(Wg, p_Wgt, CH, CH);

    k_rownorm<<<(N_NODES * 32 + 255) / 256, 256>>>();
    k_gemm<CH><<<(N_NODES + 127) / 128, 256>>>(p_h, p_Wgt, nullptr, p_xw, N_NODES);

    k_z1init<<<(N_NODES * 32 + 255) / 256, 256>>>(bg);
    k_agg<<<(N_EDGES * 32 + 255) / 256, 256>>>();

    k_z2<<<N_NODES, 256>>>(x2, W22);

    k_final<<<(N_EDGES * 32 + 255) / 256, 256>>>(out);
}

// round 12
// speedup vs baseline: 2.2641x; 1.0383x over previous
#include <cuda_runtime.h>
#include <cstdint>
#include <cstring>

#define N_NODES 10000
#define N_EDGES 320000
#define IN_DIM  512
#define CH      128

typedef unsigned long long ull;

// ---------------- scratch (__device__ globals; no allocation allowed) ----------------
__device__ int   g_is64;
__device__ int   g_eidx[2 * N_EDGES];
__device__ int   g_deg[N_NODES];
__device__ float g_dinv[N_NODES];
__device__ float g_s0[N_NODES];
__device__ float g_h[N_NODES * CH];
__device__ float g_xw[N_NODES * CH];
__device__ float g_z1[N_NODES * CH];
__device__ float g_W2t[IN_DIM * CH];   // [K][CH]
__device__ float g_Wgt[CH * CH];       // [K][CH]

// ---------------- helpers ----------------
__device__ __forceinline__ ull dup2(float x) {
    float2 t = make_float2(x, x);
    ull r; memcpy(&r, &t, 8); return r;
}
__device__ __forceinline__ float sigf(float x) { return 1.0f / (1.0f + __expf(-x)); }

// ---------------- edge index dtype detection + normalization ----------------
__global__ void k_detect(const void* ei) {
    if (threadIdx.x == 0) {
        const long long* p = (const long long*)ei;
        int ok = 1;
        for (int i = 0; i < 64; i++) {
            long long v = p[i];
            if (v < 0 || v >= N_NODES) ok = 0;
        }
        g_is64 = ok;   // if data were int32, packed pairs would be out of range
    }
}

__global__ void k_edges(const void* ei) {
    int i = blockIdx.x * blockDim.x + threadIdx.x;
    if (i < 2 * N_EDGES) {
        int v = g_is64 ? (int)((const long long*)ei)[i] : ((const int*)ei)[i];
        g_eidx[i] = v;
    }
    if (i < N_NODES) g_deg[i] = 1;  // self-loop
}

__global__ void k_deg() {
    int e = blockIdx.x * blockDim.x + threadIdx.x;
    if (e < N_EDGES) atomicAdd(&g_deg[g_eidx[N_EDGES + e]], 1);
}

__global__ void k_dinv() {
    int i = blockIdx.x * blockDim.x + threadIdx.x;
    if (i < N_NODES) g_dinv[i] = rsqrtf((float)g_deg[i]);
}

// ---------------- weight transpose: W [R][C] -> Wt [C][R] ----------------
__global__ void k_tr(const float* __restrict__ src, float* __restrict__ dst, int R, int C) {
    int idx = blockIdx.x * blockDim.x + threadIdx.x;
    if (idx < R * C) {
        int r = idx / C, c = idx % C;
        dst[c * R + r] = src[idx];
    }
}

// ---------------- GEMM: out[M][128] = A[M][K] @ Wt[K][128] (+bias) ----------------
// BM=64, BN=64, BK=32, 256 threads, TM=4, TN=4, packed f32x2 FMA.
// Grid = ceil(M/64) * 2 (N split in two 64-col halves) -> ~314 blocks, high occupancy.
template<int K>
__global__ void __launch_bounds__(256) k_gemm(const float* __restrict__ A,
                                              const float* __restrict__ Wt,
                                              const float* __restrict__ bias,
                                              float* __restrict__ out, int M) {
    __shared__ float As[64][33];      // [m][k], padded stride
    __shared__ float Ws[32][64];      // [k][n]

    int tid = threadIdx.x;
    int tx = tid & 15;      // 16 column groups of 4
    int ty = tid >> 4;      // 16 row groups of 4
    int row0 = (blockIdx.x >> 1) * 64;
    int col0 = (blockIdx.x & 1) * 64;

    ull acc[4][2];
    #pragma unroll
    for (int i = 0; i < 4; i++) { acc[i][0] = 0ull; acc[i][1] = 0ull; }

    for (int k0 = 0; k0 < K; k0 += 32) {
        // load A tile: 64 rows x 32 k (512 float4 slots, 2 per thread)
        #pragma unroll
        for (int i = 0; i < 2; i++) {
            int s = tid + i * 256;
            int m = s >> 3, kq = s & 7;
            int gm = row0 + m;
            float4 v = make_float4(0.f, 0.f, 0.f, 0.f);
            if (gm < M) v = *(const float4*)(A + (size_t)gm * K + k0 + kq * 4);
            float* dst = &As[m][kq * 4];
            dst[0] = v.x; dst[1] = v.y; dst[2] = v.z; dst[3] = v.w;
        }
        // load W tile: 32 k x 64 n (512 float4 slots, 2 per thread)
        #pragma unroll
        for (int i = 0; i < 2; i++) {
            int s = tid + i * 256;
            int kk = s >> 4, nq = s & 15;
            *(float4*)&Ws[kk][nq * 4] = *(const float4*)(Wt + (size_t)(k0 + kk) * CH + col0 + nq * 4);
        }
        __syncthreads();

        #pragma unroll
        for (int k = 0; k < 32; k++) {
            float4 b0 = *(const float4*)&Ws[k][tx * 4];
            ull bb0, bb1;
            memcpy(&bb0, &b0.x, 8); memcpy(&bb1, &b0.z, 8);
            #pragma unroll
            for (int i = 0; i < 4; i++) {
                ull aa = dup2(As[ty * 4 + i][k]);
                asm("fma.rn.f32x2 %0, %1, %2, %0;" : "+l"(acc[i][0]) : "l"(aa), "l"(bb0));
                asm("fma.rn.f32x2 %0, %1, %2, %0;" : "+l"(acc[i][1]) : "l"(aa), "l"(bb1));
            }
        }
        __syncthreads();
    }

    float4 bv = make_float4(0.f, 0.f, 0.f, 0.f);
    if (bias) bv = *(const float4*)(bias + col0 + tx * 4);
    #pragma unroll
    for (int i = 0; i < 4; i++) {
        int gm = row0 + ty * 4 + i;
        if (gm < M) {
            float2 c0, c1;
            memcpy(&c0, &acc[i][0], 8);
            memcpy(&c1, &acc[i][1], 8);
            float4 o = make_float4(c0.x + bv.x, c0.y + bv.y, c1.x + bv.z, c1.y + bv.w);
            *(float4*)(out + (size_t)gm * CH + col0 + tx * 4) = o;
        }
    }
}

// ---------------- row l2-normalize * 1.8 (in place on g_h), warp per row ----------------
__global__ void k_rownorm() {
    int g = blockIdx.x * blockDim.x + threadIdx.x;
    int row = g >> 5, lane = g & 31;
    if (row >= N_NODES) return;
    float4* h4 = (float4*)g_h;
    float4 v = h4[(size_t)row * 32 + lane];
    float ss = v.x * v.x + v.y * v.y + v.z * v.z + v.w * v.w;
    #pragma unroll
    for (int o = 16; o > 0; o >>= 1) ss += __shfl_xor_sync(0xffffffffu, ss, o);
    float s = 1.8f / fmaxf(sqrtf(ss), 1e-12f);
    v.x *= s; v.y *= s; v.z *= s; v.w *= s;
    h4[(size_t)row * 32 + lane] = v;
}

// ---------------- z1 init: z1 = bg + xw * dinv^2 (self-loop term) ----------------
__global__ void k_z1init(const float* __restrict__ bg) {
    int i4 = blockIdx.x * blockDim.x + threadIdx.x;
    if (i4 >= N_NODES * 32) return;
    int n = i4 >> 5, c4 = i4 & 31;
    float d = g_dinv[n];
    float w = d * d;
    float4 xv = ((const float4*)g_xw)[i4];
    float4 b = ((const float4*)bg)[c4];
    ((float4*)g_z1)[i4] = make_float4(b.x + xv.x * w, b.y + xv.y * w,
                                      b.z + xv.z * w, b.w + xv.w * w);
}

// ---------------- edge aggregation: z1[c] += dinv[r]*dinv[c] * xw[r], warp/edge ----------------
__global__ void __launch_bounds__(256) k_agg() {
    int g = blockIdx.x * blockDim.x + threadIdx.x;
    int e = g >> 5, lane = g & 31;
    if (e >= N_EDGES) return;
    int r = g_eidx[e], c = g_eidx[N_EDGES + e];
    float w = g_dinv[r] * g_dinv[c];
    float4 v = ((const float4*)g_xw)[(size_t)r * 32 + lane];
    float* dst = g_z1 + (size_t)c * CH + lane * 4;
    asm volatile("red.global.add.v4.f32 [%0], {%1, %2, %3, %4};"
                 :: "l"(dst), "f"(v.x * w), "f"(v.y * w), "f"(v.z * w), "f"(v.w * w)
                 : "memory");
}

// ---------------- z2 branch: one block per row, W22 from L1/L2, no smem tiles ----------------
__global__ void __launch_bounds__(256) k_z2(const float* __restrict__ x2,
                                            const float* __restrict__ W22) {
    int row = blockIdx.x;
    int tid = threadIdx.x;
    int lane = tid & 31, warp = tid >> 5;
    const float4* xr = (const float4*)(x2 + (size_t)row * N_NODES);
    const float4* w0 = (const float4*)W22;
    const float4* w1 = (const float4*)(W22 + N_NODES);

    float a = 0.f, b = 0.f;
    for (int i = tid; i < N_NODES / 4; i += 256) {
        float4 xv = __ldcs(&xr[i]);   // streamed, read once
        float4 wa = __ldg(&w0[i]);    // L1-resident after first row on this SM
        float4 wb = __ldg(&w1[i]);
        a += xv.x * wa.x + xv.y * wa.y + xv.z * wa.z + xv.w * wa.w;
        b += xv.x * wb.x + xv.y * wb.y + xv.z * wb.z + xv.w * wb.w;
    }
    #pragma unroll
    for (int o = 16; o > 0; o >>= 1) {
        a += __shfl_xor_sync(0xffffffffu, a, o);
        b += __shfl_xor_sync(0xffffffffu, b, o);
    }
    __shared__ float sa[8], sb[8];
    if (lane == 0) { sa[warp] = a; sb[warp] = b; }
    __syncthreads();
    if (tid == 0) {
        float aa = 0.f, bbv = 0.f;
        #pragma unroll
        for (int w = 0; w < 8; w++) { aa += sa[w]; bbv += sb[w]; }
        g_s0[row] = 0.8f * aa / fmaxf(sqrtf(aa * aa + bbv * bbv), 1e-12f);
    }
}

// ---------------- final per-edge decoder, warp per edge ----------------
__global__ void __launch_bounds__(256) k_final(float* __restrict__ out) {
    int g = blockIdx.x * blockDim.x + threadIdx.x;
    int e = g >> 5, lane = g & 31;
    if (e >= N_EDGES) return;
    int r = g_eidx[e], c = g_eidx[N_EDGES + e];
    const float4* z4 = (const float4*)g_z1;
    float4 a = z4[(size_t)r * 32 + lane];
    float4 b = z4[(size_t)c * 32 + lane];
    float p = a.x * b.x + a.y * b.y + a.z * b.z + a.w * b.w;
    #pragma unroll
    for (int o = 16; o > 0; o >>= 1) p += __shfl_xor_sync(0xffffffffu, p, o);
    if (lane == 0) {
        float sf = sigf(p);
        float vn = g_s0[r] + g_s0[c];
        out[e] = sf * sf + (1.0f - sf) * sigf(vn);
    }
}

// ---------------- launch ----------------
static void* sym_addr(const void* sym) {
    void* p = nullptr;
    cudaGetSymbolAddress(&p, sym);
    return p;
}

extern "C" void kernel_launch(void* const* d_in, const int* in_sizes, int n_in,
                              void* d_out, int out_size) {
    const float* x   = (const float*)d_in[0];
    const float* x2  = (const float*)d_in[1];
    const float* W2  = (const float*)d_in[2];
    const float* b2  = (const float*)d_in[3];
    const float* Wg  = (const float*)d_in[4];
    const float* bg  = (const float*)d_in[5];
    const float* W22 = (const float*)d_in[6];
    const void*  ei  = d_in[7];
    float* out = (float*)d_out;

    float* p_h   = (float*)sym_addr(g_h);
    float* p_xw  = (float*)sym_addr(g_xw);
    float* p_W2t = (float*)sym_addr(g_W2t);
    float* p_Wgt = (float*)sym_addr(g_Wgt);

    // Launch order: slot #4 (profiled) = new k_z2.
    k_detect<<<1, 32>>>(ei);                                         // 1
    k_edges<<<(2 * N_EDGES + 255) / 256, 256>>>(ei);                 // 2
    k_deg<<<(N_EDGES + 255) / 256, 256>>>();                         // 3
    k_z2<<<N_NODES, 256>>>(x2, W22);                                 // 4 <- profiled
    k_dinv<<<(N_NODES + 255) / 256, 256>>>();                        // 5
    k_tr<<<(IN_DIM * CH + 255) / 256, 256>>>(W2, p_W2t, CH, IN_DIM);
    k_tr<<<(CH * CH + 255) / 256, 256>>>(Wg, p_Wgt, CH, CH);

    k_gemm<IN_DIM><<<((N_NODES + 63) / 64) * 2, 256>>>(x, p_W2t, b2, p_h, N_NODES);
    k_rownorm<<<(N_NODES * 32 + 255) / 256, 256>>>();
    k_gemm<CH><<<((N_NODES + 63) / 64) * 2, 256>>>(p_h, p_Wgt, nullptr, p_xw, N_NODES);

    k_z1init<<<(N_NODES * 32 + 255) / 256, 256>>>(bg);
    k_agg<<<(N_EDGES * 32 + 255) / 256, 256>>>();

    k_final<<<(N_EDGES * 32 + 255) / 256, 256>>>(out);
}

// round 16
// speedup vs baseline: 2.3340x; 1.0309x over previous
#include <cuda_runtime.h>
#include <cstdint>
#include <cstring>

#define N_NODES 10000
#define N_EDGES 320000
#define IN_DIM  512
#define CH      128

typedef unsigned long long ull;

// ---------------- scratch (__device__ globals; no allocation allowed) ----------------
__device__ int   g_eidx[2 * N_EDGES];
__device__ int   g_deg[N_NODES];
__device__ float g_dinv[N_NODES];
__device__ float g_s0[N_NODES];
__device__ float g_h[N_NODES * CH];
__device__ float g_xw[N_NODES * CH];
__device__ float g_z1[N_NODES * CH];
__device__ float g_W2t[IN_DIM * CH];   // [K][CH]
__device__ float g_Wgt[CH * CH];       // [K][CH]

// ---------------- helpers ----------------
__device__ __forceinline__ ull dup2(float x) {
    float2 t = make_float2(x, x);
    ull r; memcpy(&r, &t, 8); return r;
}
__device__ __forceinline__ float sigf(float x) { return 1.0f / (1.0f + __expf(-x)); }

// ---------------- edges: detect dtype per block, convert, zero deg ----------------
__global__ void k_edges(const void* ei) {
    __shared__ int s_is64;
    if (threadIdx.x == 0) {
        const long long* p = (const long long*)ei;
        int ok = 1;
        #pragma unroll 8
        for (int i = 0; i < 64; i++) {
            long long v = p[i];
            if (v < 0 || v >= N_NODES) ok = 0;
        }
        s_is64 = ok;  // int32 data read as int64 pairs would be out of range
    }
    __syncthreads();
    int is64 = s_is64;
    int i = blockIdx.x * blockDim.x + threadIdx.x;
    if (i < 2 * N_EDGES) {
        int v = is64 ? (int)((const long long*)ei)[i] : ((const int*)ei)[i];
        g_eidx[i] = v;
    }
    if (i < N_NODES) g_deg[i] = 1;  // self-loop
}

__global__ void k_deg() {
    int e = blockIdx.x * blockDim.x + threadIdx.x;
    if (e < N_EDGES) atomicAdd(&g_deg[g_eidx[N_EDGES + e]], 1);
}

__global__ void k_dinv() {
    int i = blockIdx.x * blockDim.x + threadIdx.x;
    if (i < N_NODES) g_dinv[i] = rsqrtf((float)g_deg[i]);
}

// ---------------- fused weight transpose: W2 [128][512]->g_W2t, Wg [128][128]->g_Wgt ----
__global__ void k_tr2(const float* __restrict__ W2, const float* __restrict__ Wg) {
    int idx = blockIdx.x * blockDim.x + threadIdx.x;
    if (idx < IN_DIM * CH) {
        int r = idx / IN_DIM, c = idx % IN_DIM;      // W2 row r (out ch), col c (in dim)
        g_W2t[c * CH + r] = W2[idx];
    } else {
        int j = idx - IN_DIM * CH;
        if (j < CH * CH) {
            int r = j / CH, c = j % CH;
            g_Wgt[c * CH + r] = Wg[j];
        }
    }
}

// ---------------- GEMM: out[M][128] = A[M][K] @ Wt[K][128] (+bias) ----------------
// BM=64, BN=64, BK=32, 256 threads, TM=4, TN=4, packed f32x2 FMA.
// Optional fused z1 epilogue: z1 = zb + out * dinv[row]^2 (self-loop term of GCN).
template<int K>
__global__ void __launch_bounds__(256) k_gemm(const float* __restrict__ A,
                                              const float* __restrict__ Wt,
                                              const float* __restrict__ bias,
                                              float* __restrict__ out, int M,
                                              const float* __restrict__ dinv,
                                              const float* __restrict__ zb,
                                              float* __restrict__ z1) {
    __shared__ float As[64][33];      // [m][k], padded stride
    __shared__ float Ws[32][64];      // [k][n]

    int tid = threadIdx.x;
    int tx = tid & 15;      // 16 column groups of 4
    int ty = tid >> 4;      // 16 row groups of 4
    int row0 = (blockIdx.x >> 1) * 64;
    int col0 = (blockIdx.x & 1) * 64;

    ull acc[4][2];
    #pragma unroll
    for (int i = 0; i < 4; i++) { acc[i][0] = 0ull; acc[i][1] = 0ull; }

    for (int k0 = 0; k0 < K; k0 += 32) {
        #pragma unroll
        for (int i = 0; i < 2; i++) {
            int s = tid + i * 256;
            int m = s >> 3, kq = s & 7;
            int gm = row0 + m;
            float4 v = make_float4(0.f, 0.f, 0.f, 0.f);
            if (gm < M) v = *(const float4*)(A + (size_t)gm * K + k0 + kq * 4);
            float* dst = &As[m][kq * 4];
            dst[0] = v.x; dst[1] = v.y; dst[2] = v.z; dst[3] = v.w;
        }
        #pragma unroll
        for (int i = 0; i < 2; i++) {
            int s = tid + i * 256;
            int kk = s >> 4, nq = s & 15;
            *(float4*)&Ws[kk][nq * 4] = *(const float4*)(Wt + (size_t)(k0 + kk) * CH + col0 + nq * 4);
        }
        __syncthreads();

        #pragma unroll
        for (int k = 0; k < 32; k++) {
            float4 b0 = *(const float4*)&Ws[k][tx * 4];
            ull bb0, bb1;
            memcpy(&bb0, &b0.x, 8); memcpy(&bb1, &b0.z, 8);
            #pragma unroll
            for (int i = 0; i < 4; i++) {
                ull aa = dup2(As[ty * 4 + i][k]);
                asm("fma.rn.f32x2 %0, %1, %2, %0;" : "+l"(acc[i][0]) : "l"(aa), "l"(bb0));
                asm("fma.rn.f32x2 %0, %1, %2, %0;" : "+l"(acc[i][1]) : "l"(aa), "l"(bb1));
            }
        }
        __syncthreads();
    }

    float4 bv = make_float4(0.f, 0.f, 0.f, 0.f);
    if (bias) bv = *(const float4*)(bias + col0 + tx * 4);
    float4 zbv = make_float4(0.f, 0.f, 0.f, 0.f);
    if (z1) zbv = *(const float4*)(zb + col0 + tx * 4);
    #pragma unroll
    for (int i = 0; i < 4; i++) {
        int gm = row0 + ty * 4 + i;
        if (gm < M) {
            float2 c0, c1;
            memcpy(&c0, &acc[i][0], 8);
            memcpy(&c1, &acc[i][1], 8);
            float4 o = make_float4(c0.x + bv.x, c0.y + bv.y, c1.x + bv.z, c1.y + bv.w);
            *(float4*)(out + (size_t)gm * CH + col0 + tx * 4) = o;
            if (z1) {
                float d = dinv[gm];
                float w = d * d;
                float4 zv = make_float4(zbv.x + o.x * w, zbv.y + o.y * w,
                                        zbv.z + o.z * w, zbv.w + o.w * w);
                *(float4*)(z1 + (size_t)gm * CH + col0 + tx * 4) = zv;
            }
        }
    }
}

// ---------------- row l2-normalize * 1.8 (in place on g_h), warp per row ----------------
__global__ void k_rownorm() {
    int g = blockIdx.x * blockDim.x + threadIdx.x;
    int row = g >> 5, lane = g & 31;
    if (row >= N_NODES) return;
    float4* h4 = (float4*)g_h;
    float4 v = h4[(size_t)row * 32 + lane];
    float ss = v.x * v.x + v.y * v.y + v.z * v.z + v.w * v.w;
    #pragma unroll
    for (int o = 16; o > 0; o >>= 1) ss += __shfl_xor_sync(0xffffffffu, ss, o);
    float s = 1.8f / fmaxf(sqrtf(ss), 1e-12f);
    v.x *= s; v.y *= s; v.z *= s; v.w *= s;
    h4[(size_t)row * 32 + lane] = v;
}

// ---------------- edge aggregation: z1[c] += dinv[r]*dinv[c] * xw[r], warp/edge ----------------
__global__ void __launch_bounds__(256) k_agg() {
    int g = blockIdx.x * blockDim.x + threadIdx.x;
    int e = g >> 5, lane = g & 31;
    if (e >= N_EDGES) return;
    int r = g_eidx[e], c = g_eidx[N_EDGES + e];
    float w = g_dinv[r] * g_dinv[c];
    float4 v = ((const float4*)g_xw)[(size_t)r * 32 + lane];
    float* dst = g_z1 + (size_t)c * CH + lane * 4;
    asm volatile("red.global.add.v4.f32 [%0], {%1, %2, %3, %4};"
                 :: "l"(dst), "f"(v.x * w), "f"(v.y * w), "f"(v.z * w), "f"(v.w * w)
                 : "memory");
}

// ---------------- z2 branch: one block per row, W22 from L1/L2, no smem tiles ----------------
__global__ void __launch_bounds__(256) k_z2(const float* __restrict__ x2,
                                            const float* __restrict__ W22) {
    int row = blockIdx.x;
    int tid = threadIdx.x;
    int lane = tid & 31, warp = tid >> 5;
    const float4* xr = (const float4*)(x2 + (size_t)row * N_NODES);
    const float4* w0 = (const float4*)W22;
    const float4* w1 = (const float4*)(W22 + N_NODES);

    float a = 0.f, b = 0.f;
    for (int i = tid; i < N_NODES / 4; i += 256) {
        float4 xv = __ldcs(&xr[i]);   // streamed, read once
        float4 wa = __ldg(&w0[i]);    // L1-resident after first row on this SM
        float4 wb = __ldg(&w1[i]);
        a += xv.x * wa.x + xv.y * wa.y + xv.z * wa.z + xv.w * wa.w;
        b += xv.x * wb.x + xv.y * wb.y + xv.z * wb.z + xv.w * wb.w;
    }
    #pragma unroll
    for (int o = 16; o > 0; o >>= 1) {
        a += __shfl_xor_sync(0xffffffffu, a, o);
        b += __shfl_xor_sync(0xffffffffu, b, o);
    }
    __shared__ float sa[8], sb[8];
    if (lane == 0) { sa[warp] = a; sb[warp] = b; }
    __syncthreads();
    if (tid == 0) {
        float aa = 0.f, bbv = 0.f;
        #pragma unroll
        for (int w = 0; w < 8; w++) { aa += sa[w]; bbv += sb[w]; }
        g_s0[row] = 0.8f * aa / fmaxf(sqrtf(aa * aa + bbv * bbv), 1e-12f);
    }
}

// ---------------- final per-edge decoder, warp per edge ----------------
__global__ void __launch_bounds__(256) k_final(float* __restrict__ out) {
    int g = blockIdx.x * blockDim.x + threadIdx.x;
    int e = g >> 5, lane = g & 31;
    if (e >= N_EDGES) return;
    int r = g_eidx[e], c = g_eidx[N_EDGES + e];
    const float4* z4 = (const float4*)g_z1;
    float4 a = z4[(size_t)r * 32 + lane];
    float4 b = z4[(size_t)c * 32 + lane];
    float p = a.x * b.x + a.y * b.y + a.z * b.z + a.w * b.w;
    #pragma unroll
    for (int o = 16; o > 0; o >>= 1) p += __shfl_xor_sync(0xffffffffu, p, o);
    if (lane == 0) {
        float sf = sigf(p);
        float vn = g_s0[r] + g_s0[c];
        out[e] = sf * sf + (1.0f - sf) * sigf(vn);
    }
}

// ---------------- launch ----------------
static void* sym_addr(const void* sym) {
    void* p = nullptr;
    cudaGetSymbolAddress(&p, sym);
    return p;
}

extern "C" void kernel_launch(void* const* d_in, const int* in_sizes, int n_in,
                              void* d_out, int out_size) {
    const float* x   = (const float*)d_in[0];
    const float* x2  = (const float*)d_in[1];
    const float* W2  = (const float*)d_in[2];
    const float* b2  = (const float*)d_in[3];
    const float* Wg  = (const float*)d_in[4];
    const float* bg  = (const float*)d_in[5];
    const float* W22 = (const float*)d_in[6];
    const void*  ei  = d_in[7];
    float* out = (float*)d_out;

    float* p_h    = (float*)sym_addr(g_h);
    float* p_xw   = (float*)sym_addr(g_xw);
    float* p_z1   = (float*)sym_addr(g_z1);
    float* p_dinv = (float*)sym_addr(g_dinv);
    float* p_W2t  = (float*)sym_addr(g_W2t);
    float* p_Wgt  = (float*)sym_addr(g_Wgt);

    // One-time host-side resources (no device memory involved).
    static cudaStream_t s_side = nullptr;
    static cudaEvent_t ev_fork = nullptr, ev_join = nullptr;
    if (!s_side) {
        cudaStreamCreateWithFlags(&s_side, cudaStreamNonBlocking);
        cudaEventCreateWithFlags(&ev_fork, cudaEventDisableTiming);
        cudaEventCreateWithFlags(&ev_join, cudaEventDisableTiming);
    }

    // Fork: z2 (HBM-bound, independent) runs concurrently with the GCN chain.
    cudaEventRecord(ev_fork, 0);
    cudaStreamWaitEvent(s_side, ev_fork, 0);
    k_z2<<<N_NODES, 256, 0, s_side>>>(x2, W22);          // launch 1 (side)
    cudaEventRecord(ev_join, s_side);

    // Main chain (default/capture stream).
    k_edges<<<(2 * N_EDGES + 255) / 256, 256>>>(ei);     // launch 2
    k_tr2<<<(IN_DIM * CH + CH * CH + 255) / 256, 256>>>(W2, Wg);  // launch 3
    k_gemm<IN_DIM><<<((N_NODES + 63) / 64) * 2, 256>>>(  // launch 4 <- profiled
        x, p_W2t, b2, p_h, N_NODES, nullptr, nullptr, nullptr);
    k_deg<<<(N_EDGES + 255) / 256, 256>>>();             // launch 5
    k_dinv<<<(N_NODES + 255) / 256, 256>>>();
    k_rownorm<<<(N_NODES * 32 + 255) / 256, 256>>>();
    k_gemm<CH><<<((N_NODES + 63) / 64) * 2, 256>>>(      // fused z1 epilogue
        p_h, p_Wgt, nullptr, p_xw, N_NODES, p_dinv, bg, p_z1);
    k_agg<<<(N_EDGES * 32 + 255) / 256, 256>>>();

    // Join: final needs both z1 (chain) and s0 (side).
    cudaStreamWaitEvent(0, ev_join, 0);
    k_final<<<(N_EDGES * 32 + 255) / 256, 256>>>(out);
}